// round 7
// baseline (speedup 1.0000x reference)
#include <cuda_runtime.h>
#include <cuda_bf16.h>
#include <cstdint>

// ---------------------------------------------------------------- constants
#define NB   64
#define NT   1000
#define NI   512          // K
#define NO   256          // N
#define NM   (NB * NT)    // 64000 (M)

#define ALPHA 0.95f
#define BETA  0.90f

#define NSEG  8
#define SEGL  125         // NT / NSEG
#define NCHAN (NB * NO)   // 16384

// ---------------------------------------------------------------- scratch
__device__ __align__(256) __nv_bfloat16 g_A2[(size_t)NM * 1024];   // [A_hi | A_lo]
__device__ __align__(256) uint2         g_Wp[NO * (NI / 2)];       // {hi2, lo2} per k-pair
__device__ __align__(256) float         g_h[(size_t)NM * NO];
__device__ __align__(256) float2        g_segstate[NSEG * NCHAN];
__device__ __align__(256) float2        g_carry[NSEG * NCHAN];

// ---------------------------------------------------------------- helpers
__device__ __forceinline__ uint32_t smem_u32(const void* p) {
    uint32_t a;
    asm("{ .reg .u64 t; cvta.to.shared.u64 t, %1; cvt.u32.u64 %0, t; }"
        : "=r"(a) : "l"(p));
    return a;
}
__device__ __forceinline__ void cpasync16(uint32_t s, const void* g) {
    asm volatile("cp.async.cg.shared.global [%0], [%1], 16;\n" :: "r"(s), "l"(g));
}
#define CP_COMMIT()  asm volatile("cp.async.commit_group;" ::: "memory")
#define CP_WAIT(n)   asm volatile("cp.async.wait_group %0;" :: "n"(n) : "memory")

__device__ __forceinline__ void ldsm_x4(uint32_t* r, uint32_t addr) {
    asm volatile("ldmatrix.sync.aligned.m8n8.x4.shared.b16 {%0,%1,%2,%3}, [%4];"
                 : "=r"(r[0]), "=r"(r[1]), "=r"(r[2]), "=r"(r[3]) : "r"(addr));
}
__device__ __forceinline__ void mma16816(float* d, const uint32_t* a, const uint32_t* b) {
    asm volatile(
        "mma.sync.aligned.m16n8k16.row.col.f32.bf16.bf16.f32 "
        "{%0,%1,%2,%3}, {%4,%5,%6,%7}, {%8,%9}, {%0,%1,%2,%3};"
        : "+f"(d[0]), "+f"(d[1]), "+f"(d[2]), "+f"(d[3])
        : "r"(a[0]), "r"(a[1]), "r"(a[2]), "r"(a[3]), "r"(b[0]), "r"(b[1]));
}

// ---------------------------------------------------------------- convert A
__global__ __launch_bounds__(256)
void snn_convA(const float* __restrict__ in) {
    size_t idx = (size_t)blockIdx.x * 256 + threadIdx.x;  // 4,096,000 threads
    size_t e0  = idx * 8;
    float4 v0 = *reinterpret_cast<const float4*>(in + e0);
    float4 v1 = *reinterpret_cast<const float4*>(in + e0 + 4);
    float xs[8] = {v0.x, v0.y, v0.z, v0.w, v1.x, v1.y, v1.z, v1.w};
    __align__(16) __nv_bfloat16 hi[8];
    __align__(16) __nv_bfloat16 lo[8];
#pragma unroll
    for (int i = 0; i < 8; i++) {
        hi[i] = __float2bfloat16(xs[i]);
        lo[i] = __float2bfloat16(xs[i] - __bfloat162float(hi[i]));
    }
    size_t m = e0 >> 9;
    size_t k = e0 & 511;
    *reinterpret_cast<uint4*>(g_A2 + m * 1024 + k)       = *reinterpret_cast<uint4*>(hi);
    *reinterpret_cast<uint4*>(g_A2 + m * 1024 + 512 + k) = *reinterpret_cast<uint4*>(lo);
}

// convert W into packed {hi2, lo2} per k-pair: g_Wp[n * 256 + k/2]
__global__ __launch_bounds__(256)
void snn_convW(const float* __restrict__ W) {
    size_t idx = (size_t)blockIdx.x * 256 + threadIdx.x;  // 16384 threads
    size_t e0  = idx * 8;
    float4 v0 = *reinterpret_cast<const float4*>(W + e0);
    float4 v1 = *reinterpret_cast<const float4*>(W + e0 + 4);
    float xs[8] = {v0.x, v0.y, v0.z, v0.w, v1.x, v1.y, v1.z, v1.w};
    uint16_t hb[8], lb[8];
#pragma unroll
    for (int i = 0; i < 8; i++) {
        __nv_bfloat16 h = __float2bfloat16(xs[i]);
        __nv_bfloat16 l = __float2bfloat16(xs[i] - __bfloat162float(h));
        hb[i] = __bfloat16_as_ushort(h);
        lb[i] = __bfloat16_as_ushort(l);
    }
    size_t n  = e0 >> 9;
    size_t k  = e0 & 511;
    uint2* dst = g_Wp + n * 256 + (k >> 1);
#pragma unroll
    for (int j = 0; j < 4; j++) {
        uint2 v;
        v.x = (uint32_t)hb[2 * j] | ((uint32_t)hb[2 * j + 1] << 16);
        v.y = (uint32_t)lb[2 * j] | ((uint32_t)lb[2 * j + 1] << 16);
        dst[j] = v;
    }
}

// ---------------------------------------------------------------- GEMM
// BM=128, BN=256 (full N), BK=32, 16 chunks, 512 threads (16 warps, 4x4).
// A (hi/lo) via double-buffered cp.async + ldmatrix; W via direct LDG.64 frags.
#define KCHUNKS   16
#define OFF_AHI   0
#define OFF_ALO   (8 * 1024)
#define STAGE_SZ  (16 * 1024)
#define SMEM_DYN  (2 * STAGE_SZ)

__device__ __forceinline__ uint32_t swz_off(int row, int seg) {
    return (uint32_t)(row * 64 + ((seg ^ (row & 3)) << 4));
}

__device__ __forceinline__ void load_chunkA(uint32_t st, int bm, int kc) {
    const int tid = threadIdx.x;          // 0..511
    const int row = tid >> 2;             // 0..127
    const int seg = tid & 3;
    uint32_t so = swz_off(row, seg);
    const __nv_bfloat16* Ar = g_A2 + (size_t)(bm + row) * 1024 + kc * 32 + seg * 8;
    cpasync16(st + OFF_AHI + so, Ar);
    cpasync16(st + OFF_ALO + so, Ar + 512);
}

__global__ __launch_bounds__(512, 1)
void snn_gemm_mma() {
    extern __shared__ char smem_raw[];
    const uint32_t sbase = smem_u32(smem_raw);
    const uint32_t stg[2] = {sbase, sbase + STAGE_SZ};

    const int tid   = threadIdx.x;
    const int lane  = tid & 31;
    const int wid   = tid >> 5;          // 0..15
    const int warpM = wid >> 2;          // 0..3 -> 32 rows each
    const int warpN = wid & 3;           // 0..3 -> 64 cols each
    const int bm    = blockIdx.x * 128;

    float c[2][8][4];
#pragma unroll
    for (int mt = 0; mt < 2; mt++)
#pragma unroll
        for (int nt = 0; nt < 8; nt++)
#pragma unroll
            for (int r = 0; r < 4; r++)
                c[mt][nt][r] = 0.0f;

    // A ldmatrix lane addressing
    const int a_row = warpM * 32 + (lane & 15);   // + mt*16
    const int a_sel = lane >> 4;
    // W direct-LDG fragment base: n = warpN*64 + nt*8 + (lane>>2), kpair = (lane&3)
    const uint2* wb = g_Wp + (size_t)(warpN * 64 + (lane >> 2)) * 256 + (lane & 3);

    load_chunkA(stg[0], bm, 0);
    CP_COMMIT();

    for (int kc = 0; kc < KCHUNKS; kc++) {
        const uint32_t cur = stg[kc & 1];
        if (kc < KCHUNKS - 1) {
            load_chunkA(stg[(kc + 1) & 1], bm, kc + 1);
            CP_COMMIT();
            CP_WAIT(1);
        } else {
            CP_WAIT(0);
        }
        __syncthreads();

#pragma unroll
        for (int kk = 0; kk < 2; kk++) {
            uint32_t afh[2][4], afl[2][4];
#pragma unroll
            for (int mt = 0; mt < 2; mt++) {
                uint32_t so = swz_off(a_row + mt * 16, 2 * kk + a_sel);
                ldsm_x4(afh[mt], cur + OFF_AHI + so);
                ldsm_x4(afl[mt], cur + OFF_ALO + so);
            }
            const int kp0 = kc * 16 + kk * 8;
            // process nt in halves of 4 to bound register pressure
#pragma unroll
            for (int h = 0; h < 2; h++) {
                uint32_t bh[4][2], bl[4][2];
#pragma unroll
                for (int q = 0; q < 4; q++) {
                    const uint2* p = wb + (size_t)(h * 4 + q) * 8 * 256 + kp0;
                    uint2 w0 = p[0];       // k, k+1
                    uint2 w1 = p[4];       // k+8, k+9
                    bh[q][0] = w0.x; bh[q][1] = w1.x;
                    bl[q][0] = w0.y; bl[q][1] = w1.y;
                }
#pragma unroll
                for (int mt = 0; mt < 2; mt++)
#pragma unroll
                    for (int q = 0; q < 4; q++) {
                        mma16816(c[mt][h * 4 + q], afh[mt], bh[q]);
                        mma16816(c[mt][h * 4 + q], afh[mt], bl[q]);
                        mma16816(c[mt][h * 4 + q], afl[mt], bh[q]);
                    }
            }
        }
        __syncthreads();
    }

    // epilogue: fragments -> g_h
    const int g = lane >> 2;
    const int q = lane & 3;
#pragma unroll
    for (int mt = 0; mt < 2; mt++) {
#pragma unroll
        for (int nt = 0; nt < 8; nt++) {
            int r0  = bm + warpM * 32 + mt * 16 + g;
            int col = warpN * 64 + nt * 8 + q * 2;
            *reinterpret_cast<float2*>(g_h + (size_t)r0 * NO + col)
                = make_float2(c[mt][nt][0], c[mt][nt][1]);
            *reinterpret_cast<float2*>(g_h + (size_t)(r0 + 8) * NO + col)
                = make_float2(c[mt][nt][2], c[mt][nt][3]);
        }
    }
}

// ---------------------------------------------------------------- segmented scan
// S1: per-(segment, channel) local scan (zero init) -> end state only.
__global__ __launch_bounds__(256)
void snn_scan1() {
    const int gidx = blockIdx.x * 256 + threadIdx.x;   // 0..131071
    const int seg  = gidx >> 14;
    const int chan = gidx & (NCHAN - 1);
    const int b    = chan >> 8;
    const int o    = chan & 255;

    const float* hp = g_h + (size_t)b * NT * NO + (size_t)(seg * SEGL) * NO + o;

    float flt = 0.0f, acc = 0.0f;
    for (int t = 0; t < SEGL; t += 5) {
        float hv[5];
#pragma unroll
        for (int j = 0; j < 5; j++) hv[j] = hp[(size_t)(t + j) * NO];
#pragma unroll
        for (int j = 0; j < 5; j++) {
            float na = fmaf(BETA, acc, flt);
            flt = fmaf(ALPHA, flt, hv[j]);
            acc = na;
        }
    }
    g_segstate[seg * NCHAN + chan] = make_float2(flt, acc);
}

// S2: combine segment states into carry-in per segment (per channel).
__global__ __launch_bounds__(256)
void snn_scan2() {
    const int chan = blockIdx.x * 256 + threadIdx.x;   // 0..16383

    // propagators over SEGL homogeneous steps:
    // (1,0) -> (A_L, C_L); (0,1) -> (0, B_L)
    float f1 = 1.0f, o1 = 0.0f, o2 = 1.0f;
#pragma unroll
    for (int j = 0; j < SEGL; j++) {
        o1 = fmaf(BETA, o1, f1);
        f1 = ALPHA * f1;
        o2 = BETA * o2;
    }
    const float A_L = f1, C_L = o1, B_L = o2;

    float f = 0.0f, o = 0.0f;
#pragma unroll
    for (int s = 0; s < NSEG; s++) {
        g_carry[s * NCHAN + chan] = make_float2(f, o);
        float2 loc = g_segstate[s * NCHAN + chan];
        float fn = loc.x + A_L * f;
        float on = loc.y + B_L * o + C_L * f;
        f = fn; o = on;
    }
}

// S3: final scan per segment from true carry-in, write outputs.
__global__ __launch_bounds__(256)
void snn_scan3(float* __restrict__ out) {
    const int gidx = blockIdx.x * 256 + threadIdx.x;
    const int seg  = gidx >> 14;
    const int chan = gidx & (NCHAN - 1);
    const int b    = chan >> 8;
    const int o    = chan & 255;

    const size_t base = (size_t)b * NT * NO + (size_t)(seg * SEGL) * NO + o;
    const float* hp = g_h + base;
    float*       op = out + base;

    float2 cin = g_carry[seg * NCHAN + chan];
    float flt = cin.x, acc = cin.y;

    for (int t = 0; t < SEGL; t += 5) {
        float hv[5];
#pragma unroll
        for (int j = 0; j < 5; j++) hv[j] = hp[(size_t)(t + j) * NO];
#pragma unroll
        for (int j = 0; j < 5; j++) {
            float na = fmaf(BETA, acc, flt);   // uses OLD flt
            flt = fmaf(ALPHA, flt, hv[j]);
            acc = na;
            op[(size_t)(t + j) * NO] = acc;
        }
    }
}

// ---------------------------------------------------------------- launch
extern "C" void kernel_launch(void* const* d_in, const int* in_sizes, int n_in,
                              void* d_out, int out_size) {
    const float* inputs = (const float*)d_in[0];   // (64,1000,512) f32
    const float* W      = (const float*)d_in[1];   // (256,512) f32
    float* out          = (float*)d_out;           // (64,1000,256) f32
    (void)in_sizes; (void)n_in; (void)out_size;

    cudaFuncSetAttribute(snn_gemm_mma, cudaFuncAttributeMaxDynamicSharedMemorySize, SMEM_DYN);

    snn_convA<<<16000, 256>>>(inputs);
    snn_convW<<<64, 256>>>(W);
    snn_gemm_mma<<<500, 512, SMEM_DYN>>>();
    snn_scan1<<<512, 256>>>();
    snn_scan2<<<64, 256>>>();
    snn_scan3<<<512, 256>>>(out);
}

// round 8
// speedup vs baseline: 1.3482x; 1.3482x over previous
#include <cuda_runtime.h>
#include <cuda_fp16.h>
#include <cstdint>

// ---------------------------------------------------------------- constants
#define NB   64
#define NT   1000
#define NI   512          // K
#define NO   256          // N
#define NM   (NB * NT)    // 64000 (M)

#define ALPHA 0.95f
#define BETA  0.90f

#define NSEG  8
#define SEGL  125         // NT / NSEG
#define NCHAN (NB * NO)   // 16384

// ---------------------------------------------------------------- scratch
__device__ __align__(256) __half g_Whi[NO * NI];   // fp16 high part of W
__device__ __align__(256) __half g_Wlo[NO * NI];   // fp16 low (residual) part
__device__ __align__(256) float  g_h[(size_t)NM * NO];
__device__ __align__(256) float2 g_segstate[NSEG * NCHAN];
__device__ __align__(256) float2 g_carry[NSEG * NCHAN];

// ---------------------------------------------------------------- helpers
__device__ __forceinline__ uint32_t smem_u32(const void* p) {
    uint32_t a;
    asm("{ .reg .u64 t; cvta.to.shared.u64 t, %1; cvt.u32.u64 %0, t; }"
        : "=r"(a) : "l"(p));
    return a;
}
__device__ __forceinline__ void cpasync16(uint32_t s, const void* g) {
    asm volatile("cp.async.cg.shared.global [%0], [%1], 16;\n" :: "r"(s), "l"(g));
}
#define CP_COMMIT()  asm volatile("cp.async.commit_group;" ::: "memory")
#define CP_WAIT(n)   asm volatile("cp.async.wait_group %0;" :: "n"(n) : "memory")

__device__ __forceinline__ void ldsm_x4(uint32_t* r, uint32_t addr) {
    asm volatile("ldmatrix.sync.aligned.m8n8.x4.shared.b16 {%0,%1,%2,%3}, [%4];"
                 : "=r"(r[0]), "=r"(r[1]), "=r"(r[2]), "=r"(r[3]) : "r"(addr));
}
__device__ __forceinline__ void ldsm_x2(uint32_t* r, uint32_t addr) {
    asm volatile("ldmatrix.sync.aligned.m8n8.x2.shared.b16 {%0,%1}, [%2];"
                 : "=r"(r[0]), "=r"(r[1]) : "r"(addr));
}
__device__ __forceinline__ void mma16816h(float* d, const uint32_t* a, const uint32_t* b) {
    asm volatile(
        "mma.sync.aligned.m16n8k16.row.col.f32.f16.f16.f32 "
        "{%0,%1,%2,%3}, {%4,%5,%6,%7}, {%8,%9}, {%0,%1,%2,%3};"
        : "+f"(d[0]), "+f"(d[1]), "+f"(d[2]), "+f"(d[3])
        : "r"(a[0]), "r"(a[1]), "r"(a[2]), "r"(a[3]), "r"(b[0]), "r"(b[1]));
}

// ---------------------------------------------------------------- convert W
// Exact fp16 split: W = hi + lo with hi = rn(W), lo = rn(W - hi).
__global__ __launch_bounds__(256)
void snn_convW(const float* __restrict__ W) {
    size_t idx = (size_t)blockIdx.x * 256 + threadIdx.x;  // 16384 threads
    size_t e0  = idx * 8;
    float4 v0 = *reinterpret_cast<const float4*>(W + e0);
    float4 v1 = *reinterpret_cast<const float4*>(W + e0 + 4);
    float xs[8] = {v0.x, v0.y, v0.z, v0.w, v1.x, v1.y, v1.z, v1.w};
    __align__(16) __half hi[8];
    __align__(16) __half lo[8];
#pragma unroll
    for (int i = 0; i < 8; i++) {
        hi[i] = __float2half_rn(xs[i]);
        lo[i] = __float2half_rn(xs[i] - __half2float(hi[i]));
    }
    *reinterpret_cast<uint4*>(g_Whi + e0) = *reinterpret_cast<uint4*>(hi);
    *reinterpret_cast<uint4*>(g_Wlo + e0) = *reinterpret_cast<uint4*>(lo);
}

// ---------------------------------------------------------------- GEMM
// BM=64, BN=256, BK=32, 16 chunks, 256 threads (8 warps: 2Mx4N, warp 32x64).
// A: fp32 via cp.async, converted in-smem to fp16 per chunk. W: fp16 hi/lo smem.
// 2 passes: A*W_hi + A*W_lo.
#define KCHUNKS 16
#define ST_A32  0            // 64 rows x 128B (linear)
#define ST_A16  (8 * 1024)   // 64 rows x 64B  (swizzled)
#define ST_WHI  (12 * 1024)  // 256 rows x 64B (swizzled)
#define ST_WLO  (28 * 1024)
#define STAGE_SZ (44 * 1024)
#define SMEM_DYN (2 * STAGE_SZ)   // 88KB -> 2 CTAs/SM

__device__ __forceinline__ uint32_t swz_off(int row, int seg) {
    return (uint32_t)(row * 64 + ((seg ^ (row & 3)) << 4));
}

__device__ __forceinline__ void load_chunk(uint32_t st, const float* __restrict__ Ain,
                                           int bm, int kc) {
    const int tid = threadIdx.x;
    // A fp32: 64 rows x 8 segs of 16B = 512 ops -> 2/thread (linear layout)
#pragma unroll
    for (int i = 0; i < 2; i++) {
        int idx = tid * 2 + i;
        int row = idx >> 3;            // 0..63
        int seg = idx & 7;             // 16B segment (4 floats)
        cpasync16(st + ST_A32 + (uint32_t)(row * 128 + seg * 16),
                  Ain + (size_t)(bm + row) * NI + kc * 32 + seg * 4);
    }
    // W hi/lo: 256 rows x 4 segs = 1024 ops each -> 4/thread each
#pragma unroll
    for (int i = 0; i < 4; i++) {
        int idx = tid * 4 + i;
        int row = idx >> 2;            // 0..255
        int seg = idx & 3;
        uint32_t so = swz_off(row, seg);
        const size_t goff = (size_t)row * NI + kc * 32 + seg * 8;
        cpasync16(st + ST_WHI + so, g_Whi + goff);
        cpasync16(st + ST_WLO + so, g_Wlo + goff);
    }
}

__global__ __launch_bounds__(256, 2)
void snn_gemm_mma(const float* __restrict__ Ain) {
    extern __shared__ char smem_raw[];
    const uint32_t sbase = smem_u32(smem_raw);
    const uint32_t stg[2] = {sbase, sbase + STAGE_SZ};

    const int tid   = threadIdx.x;
    const int lane  = tid & 31;
    const int wid   = tid >> 5;          // 0..7
    const int warpM = wid >> 2;          // 0..1 -> 32 rows
    const int warpN = wid & 3;           // 0..3 -> 64 cols
    const int bm    = blockIdx.x * 64;

    float c[2][8][4];
#pragma unroll
    for (int mt = 0; mt < 2; mt++)
#pragma unroll
        for (int nt = 0; nt < 8; nt++)
#pragma unroll
            for (int r = 0; r < 4; r++)
                c[mt][nt][r] = 0.0f;

    const int a_row = warpM * 32 + (lane & 15);
    const int a_sel = lane >> 4;
    const int bl    = lane & 15;
    const int b_rr  = bl & 7;
    const int b_sel = (bl >> 3) & 1;

    // convert-thread mapping (one 16B seg of fp16 per thread)
    const int cv_row = tid >> 2;
    const int cv_seg = tid & 3;

    load_chunk(stg[0], Ain, bm, 0);
    CP_COMMIT();
    load_chunk(stg[1], Ain, bm, 1);
    CP_COMMIT();

    for (int kc = 0; kc < KCHUNKS; kc++) {
        const int s = kc & 1;
        const uint32_t cur = stg[s];
        char* const curp = smem_raw + (size_t)s * STAGE_SZ;

        if (kc < KCHUNKS - 1) { CP_WAIT(1); } else { CP_WAIT(0); }
        __syncthreads();

        // convert A fp32 -> fp16 (swizzled)
        {
            const float4* sp = reinterpret_cast<const float4*>(
                curp + ST_A32 + cv_row * 128 + cv_seg * 32);
            float4 x0 = sp[0], x1 = sp[1];
            float xs[8] = {x0.x, x0.y, x0.z, x0.w, x1.x, x1.y, x1.z, x1.w};
            __align__(16) __half hh[8];
#pragma unroll
            for (int i = 0; i < 8; i++) hh[i] = __float2half_rn(xs[i]);
            *reinterpret_cast<uint4*>(curp + ST_A16 + swz_off(cv_row, cv_seg))
                = *reinterpret_cast<uint4*>(hh);
        }
        __syncthreads();

        // mma over the chunk
#pragma unroll
        for (int kk = 0; kk < 2; kk++) {
            uint32_t af[2][4];
#pragma unroll
            for (int mt = 0; mt < 2; mt++)
                ldsm_x4(af[mt], cur + ST_A16 + swz_off(a_row + mt * 16, 2 * kk + a_sel));

#pragma unroll
            for (int h = 0; h < 2; h++) {
                uint32_t bh[4][2], blo[4][2];
#pragma unroll
                for (int q = 0; q < 4; q++) {
                    int row = warpN * 64 + (h * 4 + q) * 8 + b_rr;
                    uint32_t so = swz_off(row, 2 * kk + b_sel);
                    ldsm_x2(bh[q],  cur + ST_WHI + so);
                    ldsm_x2(blo[q], cur + ST_WLO + so);
                }
#pragma unroll
                for (int mt = 0; mt < 2; mt++)
#pragma unroll
                    for (int q = 0; q < 4; q++) {
                        mma16816h(c[mt][h * 4 + q], af[mt], bh[q]);
                        mma16816h(c[mt][h * 4 + q], af[mt], blo[q]);
                    }
            }
        }
        __syncthreads();   // all reads of stage s done

        if (kc + 2 < KCHUNKS) {
            load_chunk(cur, Ain, bm, kc + 2);
            CP_COMMIT();
        }
    }

    // epilogue: fragments -> g_h
    const int g = lane >> 2;
    const int q = lane & 3;
#pragma unroll
    for (int mt = 0; mt < 2; mt++) {
#pragma unroll
        for (int nt = 0; nt < 8; nt++) {
            int r0  = bm + warpM * 32 + mt * 16 + g;
            int col = warpN * 64 + nt * 8 + q * 2;
            *reinterpret_cast<float2*>(g_h + (size_t)r0 * NO + col)
                = make_float2(c[mt][nt][0], c[mt][nt][1]);
            *reinterpret_cast<float2*>(g_h + (size_t)(r0 + 8) * NO + col)
                = make_float2(c[mt][nt][2], c[mt][nt][3]);
        }
    }
}

// ---------------------------------------------------------------- segmented scan
__global__ __launch_bounds__(256)
void snn_scan1() {
    const int gidx = blockIdx.x * 256 + threadIdx.x;   // 0..131071
    const int seg  = gidx >> 14;
    const int chan = gidx & (NCHAN - 1);
    const int b    = chan >> 8;
    const int o    = chan & 255;

    const float* hp = g_h + (size_t)b * NT * NO + (size_t)(seg * SEGL) * NO + o;

    float flt = 0.0f, acc = 0.0f;
    for (int t = 0; t < SEGL; t += 5) {
        float hv[5];
#pragma unroll
        for (int j = 0; j < 5; j++) hv[j] = hp[(size_t)(t + j) * NO];
#pragma unroll
        for (int j = 0; j < 5; j++) {
            float na = fmaf(BETA, acc, flt);
            flt = fmaf(ALPHA, flt, hv[j]);
            acc = na;
        }
    }
    g_segstate[seg * NCHAN + chan] = make_float2(flt, acc);
}

__global__ __launch_bounds__(256)
void snn_scan2() {
    const int chan = blockIdx.x * 256 + threadIdx.x;   // 0..16383

    float f1 = 1.0f, o1 = 0.0f, o2 = 1.0f;
#pragma unroll
    for (int j = 0; j < SEGL; j++) {
        o1 = fmaf(BETA, o1, f1);
        f1 = ALPHA * f1;
        o2 = BETA * o2;
    }
    const float A_L = f1, C_L = o1, B_L = o2;

    float f = 0.0f, o = 0.0f;
#pragma unroll
    for (int s = 0; s < NSEG; s++) {
        g_carry[s * NCHAN + chan] = make_float2(f, o);
        float2 loc = g_segstate[s * NCHAN + chan];
        float fn = loc.x + A_L * f;
        float on = loc.y + B_L * o + C_L * f;
        f = fn; o = on;
    }
}

__global__ __launch_bounds__(256)
void snn_scan3(float* __restrict__ out) {
    const int gidx = blockIdx.x * 256 + threadIdx.x;
    const int seg  = gidx >> 14;
    const int chan = gidx & (NCHAN - 1);
    const int b    = chan >> 8;
    const int o    = chan & 255;

    const size_t base = (size_t)b * NT * NO + (size_t)(seg * SEGL) * NO + o;
    const float* hp = g_h + base;
    float*       op = out + base;

    float2 cin = g_carry[seg * NCHAN + chan];
    float flt = cin.x, acc = cin.y;

    for (int t = 0; t < SEGL; t += 5) {
        float hv[5];
#pragma unroll
        for (int j = 0; j < 5; j++) hv[j] = hp[(size_t)(t + j) * NO];
#pragma unroll
        for (int j = 0; j < 5; j++) {
            float na = fmaf(BETA, acc, flt);   // uses OLD flt
            flt = fmaf(ALPHA, flt, hv[j]);
            acc = na;
            op[(size_t)(t + j) * NO] = acc;
        }
    }
}

// ---------------------------------------------------------------- launch
extern "C" void kernel_launch(void* const* d_in, const int* in_sizes, int n_in,
                              void* d_out, int out_size) {
    const float* inputs = (const float*)d_in[0];   // (64,1000,512) f32
    const float* W      = (const float*)d_in[1];   // (256,512) f32
    float* out          = (float*)d_out;           // (64,1000,256) f32
    (void)in_sizes; (void)n_in; (void)out_size;

    cudaFuncSetAttribute(snn_gemm_mma, cudaFuncAttributeMaxDynamicSharedMemorySize, SMEM_DYN);

    snn_convW<<<64, 256>>>(W);
    snn_gemm_mma<<<NM / 64, 256, SMEM_DYN>>>(inputs);
    snn_scan1<<<512, 256>>>();
    snn_scan2<<<64, 256>>>();
    snn_scan3<<<512, 256>>>(out);
}

// round 9
// speedup vs baseline: 2.1497x; 1.5945x over previous
#include <cuda_runtime.h>
#include <cuda_fp16.h>
#include <cstdint>

// ---------------------------------------------------------------- constants
#define NB   64
#define NT   1000
#define NI   512          // K
#define NO   256          // N
#define NM   (NB * NT)    // 64000 (M)

#define ALPHA 0.95f
#define BETA  0.90f

#define NSEG  8
#define SEGL  125         // NT / NSEG
#define NCHAN (NB * NO)   // 16384

#define KCHUNKS   16
#define WCHUNK_BY 32768   // packed W chunk bytes (hi 16K + lo 16K)

// ---------------------------------------------------------------- scratch
// Packed W: per k-chunk, the exact smem image (swizzled): [WHI 16KB | WLO 16KB]
__device__ __align__(256) unsigned char g_Wpk[KCHUNKS * WCHUNK_BY];
__device__ __align__(256) float  g_h[(size_t)NM * NO];
__device__ __align__(256) float2 g_segstate[NSEG * NCHAN];

// ---------------------------------------------------------------- helpers
__device__ __forceinline__ uint32_t smem_u32(const void* p) {
    uint32_t a;
    asm("{ .reg .u64 t; cvta.to.shared.u64 t, %1; cvt.u32.u64 %0, t; }"
        : "=r"(a) : "l"(p));
    return a;
}
__device__ __forceinline__ void cpasync16(uint32_t s, const void* g) {
    asm volatile("cp.async.cg.shared.global [%0], [%1], 16;\n" :: "r"(s), "l"(g));
}
#define CP_COMMIT()  asm volatile("cp.async.commit_group;" ::: "memory")
#define CP_WAIT(n)   asm volatile("cp.async.wait_group %0;" :: "n"(n) : "memory")

#define MBAR_INIT(a, c) \
    asm volatile("mbarrier.init.shared.b64 [%0], %1;" :: "r"(a), "r"((uint32_t)(c)) : "memory")
#define MBAR_EXPECT_TX(a, b) \
    asm volatile("mbarrier.arrive.expect_tx.shared.b64 _, [%0], %1;" \
                 :: "r"(a), "r"((uint32_t)(b)) : "memory")
__device__ __forceinline__ void mbar_wait(uint32_t addr, uint32_t parity) {
    asm volatile(
        "{\n .reg .pred P;\n"
        "W_%=: mbarrier.try_wait.parity.acquire.cta.shared::cta.b64 P, [%0], %1;\n"
        " @!P bra W_%=;\n}"
        :: "r"(addr), "r"(parity) : "memory");
}
__device__ __forceinline__ void bulk_ld(uint32_t dst, const void* src,
                                        uint32_t bytes, uint32_t mbar) {
    asm volatile(
        "cp.async.bulk.shared::cluster.global.mbarrier::complete_tx::bytes "
        "[%0], [%1], %2, [%3];"
        :: "r"(dst), "l"(src), "r"(bytes), "r"(mbar) : "memory");
}

__device__ __forceinline__ void ldsm_x4(uint32_t* r, uint32_t addr) {
    asm volatile("ldmatrix.sync.aligned.m8n8.x4.shared.b16 {%0,%1,%2,%3}, [%4];"
                 : "=r"(r[0]), "=r"(r[1]), "=r"(r[2]), "=r"(r[3]) : "r"(addr));
}
__device__ __forceinline__ void ldsm_x2(uint32_t* r, uint32_t addr) {
    asm volatile("ldmatrix.sync.aligned.m8n8.x2.shared.b16 {%0,%1}, [%2];"
                 : "=r"(r[0]), "=r"(r[1]) : "r"(addr));
}
__device__ __forceinline__ void mma16816h(float* d, const uint32_t* a, const uint32_t* b) {
    asm volatile(
        "mma.sync.aligned.m16n8k16.row.col.f32.f16.f16.f32 "
        "{%0,%1,%2,%3}, {%4,%5,%6,%7}, {%8,%9}, {%0,%1,%2,%3};"
        : "+f"(d[0]), "+f"(d[1]), "+f"(d[2]), "+f"(d[3])
        : "r"(a[0]), "r"(a[1]), "r"(a[2]), "r"(a[3]), "r"(b[0]), "r"(b[1]));
}

__device__ __host__ __forceinline__ uint32_t swz_off(int row, int seg) {
    return (uint32_t)(row * 64 + ((seg ^ (row & 3)) << 4));
}

// ---------------------------------------------------------------- convert+pack W
// W = hi + lo (exact fp16 split). Pack per k-chunk into the final smem image.
__global__ __launch_bounds__(256)
void snn_convW(const float* __restrict__ W) {
    int idx = blockIdx.x * 256 + threadIdx.x;     // 0..16383
    int n   = idx >> 6;                           // 0..255
    int k0  = (idx & 63) << 3;                    // 0..504 step 8
    float4 v0 = *reinterpret_cast<const float4*>(W + (size_t)n * NI + k0);
    float4 v1 = *reinterpret_cast<const float4*>(W + (size_t)n * NI + k0 + 4);
    float xs[8] = {v0.x, v0.y, v0.z, v0.w, v1.x, v1.y, v1.z, v1.w};
    __align__(16) __half hi[8];
    __align__(16) __half lo[8];
#pragma unroll
    for (int i = 0; i < 8; i++) {
        hi[i] = __float2half_rn(xs[i]);
        lo[i] = __float2half_rn(xs[i] - __half2float(hi[i]));
    }
    int kc  = k0 >> 5;
    int seg = (k0 & 31) >> 3;
    uint32_t off = swz_off(n, seg);
    unsigned char* base = g_Wpk + (size_t)kc * WCHUNK_BY;
    *reinterpret_cast<uint4*>(base + off)         = *reinterpret_cast<uint4*>(hi);
    *reinterpret_cast<uint4*>(base + 16384 + off) = *reinterpret_cast<uint4*>(lo);
}

// ---------------------------------------------------------------- GEMM
// BM=64, BN=256, BK=32, 16 chunks, 256 threads (8 warps: 2Mx4N, warp 32x64).
// A: fp32 cp.async + in-smem cvt to fp16. W: ONE cp.async.bulk (32KB) per chunk.
#define ST_A32  0            // 64 rows x 128B (linear fp32)
#define ST_A16  (8 * 1024)   // 64 rows x 64B  (swizzled fp16)
#define ST_WHI  (12 * 1024)  // 256 rows x 64B (swizzled)
#define ST_WLO  (28 * 1024)
#define STAGE_SZ (44 * 1024)
#define HDR      1024
#define SMEM_DYN (HDR + 2 * STAGE_SZ)   // ~89KB -> 2 CTAs/SM

__device__ __forceinline__ void issue_stage(uint32_t st, uint32_t mbar,
                                            const float* __restrict__ Ain,
                                            int bm, int kc) {
    // W: single bulk copy, elected thread (includes expect_tx)
    if (threadIdx.x == 0) {
        MBAR_EXPECT_TX(mbar, WCHUNK_BY);
        bulk_ld(st + ST_WHI, g_Wpk + (size_t)kc * WCHUNK_BY, WCHUNK_BY, mbar);
    }
    // A fp32: 64 rows x 8 segs of 16B = 512 ops -> 2/thread
    const int tid = threadIdx.x;
#pragma unroll
    for (int i = 0; i < 2; i++) {
        int idx = tid * 2 + i;
        int row = idx >> 3;            // 0..63
        int seg = idx & 7;             // 16B segment (4 floats)
        cpasync16(st + ST_A32 + (uint32_t)(row * 128 + seg * 16),
                  Ain + (size_t)(bm + row) * NI + kc * 32 + seg * 4);
    }
    CP_COMMIT();
}

__global__ __launch_bounds__(256, 2)
void snn_gemm_mma(const float* __restrict__ Ain) {
    extern __shared__ char smem_raw[];
    const uint32_t sbase = smem_u32(smem_raw);
    const uint32_t mbar[2] = {sbase, sbase + 8};
    const uint32_t stg[2]  = {sbase + HDR, sbase + HDR + STAGE_SZ};

    const int tid   = threadIdx.x;
    const int lane  = tid & 31;
    const int wid   = tid >> 5;          // 0..7
    const int warpM = wid >> 2;          // 0..1 -> 32 rows
    const int warpN = wid & 3;           // 0..3 -> 64 cols
    const int bm    = blockIdx.x * 64;

    if (tid == 0) { MBAR_INIT(mbar[0], 1); MBAR_INIT(mbar[1], 1); }
    __syncthreads();

    float c[2][8][4];
#pragma unroll
    for (int mt = 0; mt < 2; mt++)
#pragma unroll
        for (int nt = 0; nt < 8; nt++)
#pragma unroll
            for (int r = 0; r < 4; r++)
                c[mt][nt][r] = 0.0f;

    const int a_row = warpM * 32 + (lane & 15);
    const int a_sel = lane >> 4;
    const int bl    = lane & 15;
    const int b_rr  = bl & 7;
    const int b_sel = (bl >> 3) & 1;

    const int cv_row = tid >> 2;     // A cvt mapping: 64 rows x 4 thr/row
    const int cv_seg = tid & 3;      // each thread: 8 fp32 -> 8 fp16 (16B out)

    issue_stage(stg[0], mbar[0], Ain, bm, 0);
    issue_stage(stg[1], mbar[1], Ain, bm, 1);

    uint32_t ph[2] = {0, 0};

    for (int kc = 0; kc < KCHUNKS; kc++) {
        const int s = kc & 1;
        const uint32_t cur = stg[s];
        char* const curp = smem_raw + HDR + (size_t)s * STAGE_SZ;

        if (kc < KCHUNKS - 1) { CP_WAIT(1); } else { CP_WAIT(0); }
        mbar_wait(mbar[s], ph[s]);
        ph[s] ^= 1;
        __syncthreads();

        // convert A fp32 -> fp16 (swizzled)
        {
            const float4* sp = reinterpret_cast<const float4*>(
                curp + ST_A32 + cv_row * 128 + cv_seg * 32);
            float4 x0 = sp[0], x1 = sp[1];
            float xs[8] = {x0.x, x0.y, x0.z, x0.w, x1.x, x1.y, x1.z, x1.w};
            __align__(16) __half hh[8];
#pragma unroll
            for (int i = 0; i < 8; i++) hh[i] = __float2half_rn(xs[i]);
            *reinterpret_cast<uint4*>(curp + ST_A16 + swz_off(cv_row, cv_seg))
                = *reinterpret_cast<uint4*>(hh);
        }
        __syncthreads();

        // mma over the chunk (2 passes: W_hi, W_lo)
#pragma unroll
        for (int kk = 0; kk < 2; kk++) {
            uint32_t af[2][4];
#pragma unroll
            for (int mt = 0; mt < 2; mt++)
                ldsm_x4(af[mt], cur + ST_A16 + swz_off(a_row + mt * 16, 2 * kk + a_sel));

#pragma unroll
            for (int h = 0; h < 2; h++) {
                uint32_t bh[4][2], blo[4][2];
#pragma unroll
                for (int q = 0; q < 4; q++) {
                    int row = warpN * 64 + (h * 4 + q) * 8 + b_rr;
                    uint32_t so = swz_off(row, 2 * kk + b_sel);
                    ldsm_x2(bh[q],  cur + ST_WHI + so);
                    ldsm_x2(blo[q], cur + ST_WLO + so);
                }
#pragma unroll
                for (int mt = 0; mt < 2; mt++)
#pragma unroll
                    for (int q = 0; q < 4; q++) {
                        mma16816h(c[mt][h * 4 + q], af[mt], bh[q]);
                        mma16816h(c[mt][h * 4 + q], af[mt], blo[q]);
                    }
            }
        }
        __syncthreads();   // all reads of stage s done

        if (kc + 2 < KCHUNKS)
            issue_stage(cur, mbar[s], Ain, bm, kc + 2);
    }

    // epilogue: fragments -> g_h
    const int g = lane >> 2;
    const int q = lane & 3;
#pragma unroll
    for (int mt = 0; mt < 2; mt++) {
#pragma unroll
        for (int nt = 0; nt < 8; nt++) {
            int r0  = bm + warpM * 32 + mt * 16 + g;
            int col = warpN * 64 + nt * 8 + q * 2;
            *reinterpret_cast<float2*>(g_h + (size_t)r0 * NO + col)
                = make_float2(c[mt][nt][0], c[mt][nt][1]);
            *reinterpret_cast<float2*>(g_h + (size_t)(r0 + 8) * NO + col)
                = make_float2(c[mt][nt][2], c[mt][nt][3]);
        }
    }
}

// ---------------------------------------------------------------- segmented scan
// S1: per-(segment, channel) local scan (zero init) -> end state.
__global__ __launch_bounds__(256)
void snn_scan1() {
    const int gidx = blockIdx.x * 256 + threadIdx.x;   // 0..131071
    const int seg  = gidx >> 14;
    const int chan = gidx & (NCHAN - 1);
    const int b    = chan >> 8;
    const int o    = chan & 255;

    const float* hp = g_h + (size_t)b * NT * NO + (size_t)(seg * SEGL) * NO + o;

    float flt = 0.0f, acc = 0.0f;
    for (int t = 0; t < SEGL; t += 5) {
        float hv[5];
#pragma unroll
        for (int j = 0; j < 5; j++) hv[j] = hp[(size_t)(t + j) * NO];
#pragma unroll
        for (int j = 0; j < 5; j++) {
            float na = fmaf(BETA, acc, flt);
            flt = fmaf(ALPHA, flt, hv[j]);
            acc = na;
        }
    }
    g_segstate[seg * NCHAN + chan] = make_float2(flt, acc);
}

// one-segment propagator (compile-time): (f,o) -> (A*f, C*f + B*o)
struct P3 { float A, B, C; };
__host__ __device__ constexpr P3 seg_prop() {
    float f1 = 1.0f, o1 = 0.0f, o2 = 1.0f;
    for (int j = 0; j < SEGL; j++) {
        o1 = BETA * o1 + f1;
        f1 = ALPHA * f1;
        o2 = BETA * o2;
    }
    return {f1, o2, o1};
}

// S3: combine carries inline, then final scan + output.
__global__ __launch_bounds__(256)
void snn_scan3(float* __restrict__ out) {
    const int gidx = blockIdx.x * 256 + threadIdx.x;
    const int seg  = gidx >> 14;
    const int chan = gidx & (NCHAN - 1);
    const int b    = chan >> 8;
    const int o    = chan & 255;

    constexpr P3 P1 = seg_prop();

    // carry-in = sum over s < seg of P^(seg-1-s) * state_s
    float flt = 0.0f, acc = 0.0f;
    {
        float Aj = 1.0f, Bj = 1.0f, Cj = 0.0f;   // P^0 = I
        for (int j = 0; j < seg; j++) {          // j = seg-1-s, s = seg-1-j
            float2 st = g_segstate[(seg - 1 - j) * NCHAN + chan];
            flt += Aj * st.x;
            acc += Cj * st.x + Bj * st.y;
            // P^(j+1) = P1 * P^j
            float An = P1.A * Aj;
            float Cn = P1.C * Aj + P1.B * Cj;
            float Bn = P1.B * Bj;
            Aj = An; Bj = Bn; Cj = Cn;
        }
    }

    const size_t base = (size_t)b * NT * NO + (size_t)(seg * SEGL) * NO + o;
    const float* hp = g_h + base;
    float*       op = out + base;

    for (int t = 0; t < SEGL; t += 5) {
        float hv[5];
#pragma unroll
        for (int j = 0; j < 5; j++) hv[j] = hp[(size_t)(t + j) * NO];
#pragma unroll
        for (int j = 0; j < 5; j++) {
            float na = fmaf(BETA, acc, flt);   // uses OLD flt
            flt = fmaf(ALPHA, flt, hv[j]);
            acc = na;
            op[(size_t)(t + j) * NO] = acc;
        }
    }
}

// ---------------------------------------------------------------- launch
extern "C" void kernel_launch(void* const* d_in, const int* in_sizes, int n_in,
                              void* d_out, int out_size) {
    const float* inputs = (const float*)d_in[0];   // (64,1000,512) f32
    const float* W      = (const float*)d_in[1];   // (256,512) f32
    float* out          = (float*)d_out;           // (64,1000,256) f32
    (void)in_sizes; (void)n_in; (void)out_size;

    cudaFuncSetAttribute(snn_gemm_mma, cudaFuncAttributeMaxDynamicSharedMemorySize, SMEM_DYN);

    snn_convW<<<64, 256>>>(W);
    snn_gemm_mma<<<NM / 64, 256, SMEM_DYN>>>(inputs);
    snn_scan1<<<512, 256>>>();
    snn_scan3<<<512, 256>>>(out);
}

// round 12
// speedup vs baseline: 2.3932x; 1.1133x over previous
#include <cuda_runtime.h>
#include <cuda_fp16.h>
#include <cstdint>

// ---------------------------------------------------------------- constants
#define NB   64
#define NT   1000
#define NI   512          // K
#define NO   256          // N
#define NM   (NB * NT)    // 64000 (M)

#define ALPHA 0.95f
#define BETA  0.90f

#define NSEG  8
#define SEGL  125         // NT / NSEG
#define NCHAN (NB * NO)   // 16384

#define KCHUNKS   16
#define WCHUNK_BY 16384   // packed W chunk bytes (fp16, swizzled smem image)

// ---------------------------------------------------------------- scratch
__device__ __align__(256) unsigned char g_Wpk[KCHUNKS * WCHUNK_BY];
__device__ __align__(256) float  g_h[(size_t)NM * NO];
__device__ __align__(256) float2 g_segstate[NSEG * NCHAN];

// ---------------------------------------------------------------- helpers
__device__ __forceinline__ uint32_t smem_u32(const void* p) {
    uint32_t a;
    asm("{ .reg .u64 t; cvta.to.shared.u64 t, %1; cvt.u32.u64 %0, t; }"
        : "=r"(a) : "l"(p));
    return a;
}
#define MBAR_INIT(a, c) \
    asm volatile("mbarrier.init.shared.b64 [%0], %1;" :: "r"(a), "r"((uint32_t)(c)) : "memory")
#define MBAR_EXPECT_TX(a, b) \
    asm volatile("mbarrier.arrive.expect_tx.shared.b64 _, [%0], %1;" \
                 :: "r"(a), "r"((uint32_t)(b)) : "memory")
__device__ __forceinline__ void mbar_wait(uint32_t addr, uint32_t parity) {
    asm volatile(
        "{\n .reg .pred P;\n"
        "W_%=: mbarrier.try_wait.parity.acquire.cta.shared::cta.b64 P, [%0], %1;\n"
        " @!P bra W_%=;\n}"
        :: "r"(addr), "r"(parity) : "memory");
}
__device__ __forceinline__ void bulk_ld(uint32_t dst, const void* src,
                                        uint32_t bytes, uint32_t mbar) {
    asm volatile(
        "cp.async.bulk.shared::cluster.global.mbarrier::complete_tx::bytes "
        "[%0], [%1], %2, [%3];"
        :: "r"(dst), "l"(src), "r"(bytes), "r"(mbar) : "memory");
}
__device__ __forceinline__ void ldsm_x4(uint32_t* r, uint32_t addr) {
    asm volatile("ldmatrix.sync.aligned.m8n8.x4.shared.b16 {%0,%1,%2,%3}, [%4];"
                 : "=r"(r[0]), "=r"(r[1]), "=r"(r[2]), "=r"(r[3]) : "r"(addr));
}
__device__ __forceinline__ void ldsm_x2(uint32_t* r, uint32_t addr) {
    asm volatile("ldmatrix.sync.aligned.m8n8.x2.shared.b16 {%0,%1}, [%2];"
                 : "=r"(r[0]), "=r"(r[1]) : "r"(addr));
}
__device__ __forceinline__ void mma16816h(float* d, const uint32_t* a, const uint32_t* b) {
    asm volatile(
        "mma.sync.aligned.m16n8k16.row.col.f32.f16.f16.f32 "
        "{%0,%1,%2,%3}, {%4,%5,%6,%7}, {%8,%9}, {%0,%1,%2,%3};"
        : "+f"(d[0]), "+f"(d[1]), "+f"(d[2]), "+f"(d[3])
        : "r"(a[0]), "r"(a[1]), "r"(a[2]), "r"(a[3]), "r"(b[0]), "r"(b[1]));
}
__device__ __host__ __forceinline__ uint32_t swz_off(int row, int seg) {
    return (uint32_t)(row * 64 + ((seg ^ (row & 3)) << 4));
}

// ---------------------------------------------------------------- convert+pack W
// Single fp16 image per k-chunk (swizzled smem layout, bulk-copy ready).
__global__ __launch_bounds__(256)
void snn_convW(const float* __restrict__ W) {
    int idx = blockIdx.x * 256 + threadIdx.x;     // 0..16383
    int n   = idx >> 6;                           // 0..255
    int k0  = (idx & 63) << 3;                    // 0..504 step 8
    float4 v0 = *reinterpret_cast<const float4*>(W + (size_t)n * NI + k0);
    float4 v1 = *reinterpret_cast<const float4*>(W + (size_t)n * NI + k0 + 4);
    float xs[8] = {v0.x, v0.y, v0.z, v0.w, v1.x, v1.y, v1.z, v1.w};
    __align__(16) __half hh[8];
#pragma unroll
    for (int i = 0; i < 8; i++) hh[i] = __float2half_rn(xs[i]);
    int kc  = k0 >> 5;
    int seg = (k0 & 31) >> 3;
    *reinterpret_cast<uint4*>(g_Wpk + (size_t)kc * WCHUNK_BY + swz_off(n, seg))
        = *reinterpret_cast<uint4*>(hh);
}

// ---------------------------------------------------------------- GEMM
// BM=64, BN=256, BK=32, 16 chunks, 256 threads (8 warps: 2Mx4N, warp 32x64).
// Single fp16 pass. A: 64x 128B row bulk copies + in-smem cvt. W: one 16KB bulk.
#define ST_A32  0            // 64 rows x 128B (linear fp32)
#define ST_A16  (8 * 1024)   // 64 rows x 64B  (swizzled fp16)
#define ST_W    (12 * 1024)  // 256 rows x 64B (swizzled fp16)
#define STAGE_SZ (28 * 1024)
#define HDR      1024
#define SMEM_DYN (HDR + 2 * STAGE_SZ)   // 57KB -> 2 CTAs/SM
#define STAGE_TX (8192 + WCHUNK_BY)     // A 8KB + W 16KB

__device__ __forceinline__ void issue_stage(uint32_t st, uint32_t mbar,
                                            const float* __restrict__ Ain,
                                            int bm, int kc) {
    const int tid = threadIdx.x;
    if (tid == 0) {
        MBAR_EXPECT_TX(mbar, STAGE_TX);
        bulk_ld(st + ST_W, g_Wpk + (size_t)kc * WCHUNK_BY, WCHUNK_BY, mbar);
    }
    if (tid < 64) {  // one 128B row slice per thread (128B-aligned in gmem)
        bulk_ld(st + ST_A32 + (uint32_t)tid * 128,
                Ain + (size_t)(bm + tid) * NI + kc * 32, 128, mbar);
    }
}

__global__ __launch_bounds__(256, 2)
void snn_gemm_mma(const float* __restrict__ Ain) {
    extern __shared__ char smem_raw[];
    const uint32_t sbase = smem_u32(smem_raw);
    const uint32_t mbar[2] = {sbase, sbase + 8};
    const uint32_t stg[2]  = {sbase + HDR, sbase + HDR + STAGE_SZ};

    const int tid   = threadIdx.x;
    const int lane  = tid & 31;
    const int wid   = tid >> 5;          // 0..7
    const int warpM = wid >> 2;          // 0..1 -> 32 rows
    const int warpN = wid & 3;           // 0..3 -> 64 cols
    const int bm    = blockIdx.x * 64;

    if (tid == 0) { MBAR_INIT(mbar[0], 1); MBAR_INIT(mbar[1], 1); }
    __syncthreads();

    float c[2][8][4];
#pragma unroll
    for (int mt = 0; mt < 2; mt++)
#pragma unroll
        for (int nt = 0; nt < 8; nt++)
#pragma unroll
            for (int r = 0; r < 4; r++)
                c[mt][nt][r] = 0.0f;

    const int a_row = warpM * 32 + (lane & 15);
    const int a_sel = lane >> 4;
    const int bl    = lane & 15;
    const int b_rr  = bl & 7;
    const int b_sel = (bl >> 3) & 1;

    const int cv_row = tid >> 2;     // A cvt: 64 rows x 4 thr/row, 8 fp32 each
    const int cv_seg = tid & 3;

    issue_stage(stg[0], mbar[0], Ain, bm, 0);
    issue_stage(stg[1], mbar[1], Ain, bm, 1);

    uint32_t ph[2] = {0, 0};

    for (int kc = 0; kc < KCHUNKS; kc++) {
        const int s = kc & 1;
        const uint32_t cur = stg[s];
        char* const curp = smem_raw + HDR + (size_t)s * STAGE_SZ;

        mbar_wait(mbar[s], ph[s]);
        ph[s] ^= 1;
        __syncthreads();

        // convert A fp32 -> fp16 (swizzled)
        {
            const float4* sp = reinterpret_cast<const float4*>(
                curp + ST_A32 + cv_row * 128 + cv_seg * 32);
            float4 x0 = sp[0], x1 = sp[1];
            __align__(16) __half2 hh[4];
            hh[0] = __floats2half2_rn(x0.x, x0.y);
            hh[1] = __floats2half2_rn(x0.z, x0.w);
            hh[2] = __floats2half2_rn(x1.x, x1.y);
            hh[3] = __floats2half2_rn(x1.z, x1.w);
            *reinterpret_cast<uint4*>(curp + ST_A16 + swz_off(cv_row, cv_seg))
                = *reinterpret_cast<const uint4*>(hh);
        }
        __syncthreads();

        // mma over the chunk (single fp16 pass)
#pragma unroll
        for (int kk = 0; kk < 2; kk++) {
            uint32_t af[2][4];
#pragma unroll
            for (int mt = 0; mt < 2; mt++)
                ldsm_x4(af[mt], cur + ST_A16 + swz_off(a_row + mt * 16, 2 * kk + a_sel));

#pragma unroll
            for (int h = 0; h < 2; h++) {
                uint32_t bh[4][2];
#pragma unroll
                for (int q = 0; q < 4; q++) {
                    int row = warpN * 64 + (h * 4 + q) * 8 + b_rr;
                    ldsm_x2(bh[q], cur + ST_W + swz_off(row, 2 * kk + b_sel));
                }
#pragma unroll
                for (int mt = 0; mt < 2; mt++)
#pragma unroll
                    for (int q = 0; q < 4; q++)
                        mma16816h(c[mt][h * 4 + q], af[mt], bh[q]);
            }
        }
        __syncthreads();   // all reads of stage s done

        if (kc + 2 < KCHUNKS)
            issue_stage(cur, mbar[s], Ain, bm, kc + 2);
    }

    // epilogue: fragments -> g_h
    const int g = lane >> 2;
    const int q = lane & 3;
#pragma unroll
    for (int mt = 0; mt < 2; mt++) {
#pragma unroll
        for (int nt = 0; nt < 8; nt++) {
            int r0  = bm + warpM * 32 + mt * 16 + g;
            int col = warpN * 64 + nt * 8 + q * 2;
            *reinterpret_cast<float2*>(g_h + (size_t)r0 * NO + col)
                = make_float2(c[mt][nt][0], c[mt][nt][1]);
            *reinterpret_cast<float2*>(g_h + (size_t)(r0 + 8) * NO + col)
                = make_float2(c[mt][nt][2], c[mt][nt][3]);
        }
    }
}

// ---------------------------------------------------------------- segmented scan
__global__ __launch_bounds__(256)
void snn_scan1() {
    const int gidx = blockIdx.x * 256 + threadIdx.x;   // 0..131071
    const int seg  = gidx >> 14;
    const int chan = gidx & (NCHAN - 1);
    const int b    = chan >> 8;
    const int o    = chan & 255;

    const float* hp = g_h + (size_t)b * NT * NO + (size_t)(seg * SEGL) * NO + o;

    float flt = 0.0f, acc = 0.0f;
    for (int t = 0; t < SEGL; t += 5) {
        float hv[5];
#pragma unroll
        for (int j = 0; j < 5; j++) hv[j] = hp[(size_t)(t + j) * NO];
#pragma unroll
        for (int j = 0; j < 5; j++) {
            float na = fmaf(BETA, acc, flt);
            flt = fmaf(ALPHA, flt, hv[j]);
            acc = na;
        }
    }
    g_segstate[seg * NCHAN + chan] = make_float2(flt, acc);
}

struct P3 { float A, B, C; };
__host__ __device__ constexpr P3 seg_prop() {
    float f1 = 1.0f, o1 = 0.0f, o2 = 1.0f;
    for (int j = 0; j < SEGL; j++) {
        o1 = BETA * o1 + f1;
        f1 = ALPHA * f1;
        o2 = BETA * o2;
    }
    return {f1, o2, o1};
}

__global__ __launch_bounds__(256)
void snn_scan3(float* __restrict__ out) {
    const int gidx = blockIdx.x * 256 + threadIdx.x;
    const int seg  = gidx >> 14;
    const int chan = gidx & (NCHAN - 1);
    const int b    = chan >> 8;
    const int o    = chan & 255;

    constexpr P3 P1 = seg_prop();

    float flt = 0.0f, acc = 0.0f;
    {
        float Aj = 1.0f, Bj = 1.0f, Cj = 0.0f;   // P^0 = I
        for (int j = 0; j < seg; j++) {          // s = seg-1-j
            float2 st = g_segstate[(seg - 1 - j) * NCHAN + chan];
            flt += Aj * st.x;
            acc += Cj * st.x + Bj * st.y;
            float An = P1.A * Aj;
            float Cn = P1.C * Aj + P1.B * Cj;
            float Bn = P1.B * Bj;
            Aj = An; Bj = Bn; Cj = Cn;
        }
    }

    const size_t base = (size_t)b * NT * NO + (size_t)(seg * SEGL) * NO + o;
    const float* hp = g_h + base;
    float*       op = out + base;

    for (int t = 0; t < SEGL; t += 5) {
        float hv[5];
#pragma unroll
        for (int j = 0; j < 5; j++) hv[j] = hp[(size_t)(t + j) * NO];
#pragma unroll
        for (int j = 0; j < 5; j++) {
            float na = fmaf(BETA, acc, flt);   // uses OLD flt
            flt = fmaf(ALPHA, flt, hv[j]);
            acc = na;
            op[(size_t)(t + j) * NO] = acc;
        }
    }
}

// ---------------------------------------------------------------- launch
extern "C" void kernel_launch(void* const* d_in, const int* in_sizes, int n_in,
                              void* d_out, int out_size) {
    const float* inputs = (const float*)d_in[0];   // (64,1000,512) f32
    const float* W      = (const float*)d_in[1];   // (256,512) f32
    float* out          = (float*)d_out;           // (64,1000,256) f32
    (void)in_sizes; (void)n_in; (void)out_size;

    cudaFuncSetAttribute(snn_gemm_mma, cudaFuncAttributeMaxDynamicSharedMemorySize, SMEM_DYN);

    snn_convW<<<64, 256>>>(W);
    snn_gemm_mma<<<NM / 64, 256, SMEM_DYN>>>(inputs);
    snn_scan1<<<512, 256>>>();
    snn_scan3<<<512, 256>>>(out);
}

// round 14
// speedup vs baseline: 2.8601x; 1.1951x over previous
#include <cuda_runtime.h>
#include <cuda_fp16.h>
#include <cstdint>

// ---------------------------------------------------------------- constants
#define NB   64
#define NT   1000
#define NI   512          // K
#define NO   256          // N
#define NM   (NB * NT)    // 64000 (M)

#define ALPHA 0.95f
#define BETA  0.90f

#define NSEG  8
#define SEGL  125         // NT / NSEG
#define NCHAN (NB * NO)   // 16384

#define KCHUNKS   16
#define WCHUNK_BY 16384   // packed W chunk bytes (fp16, swizzled smem image)

// ---------------------------------------------------------------- scratch
__device__ __align__(256) unsigned char g_Wpk[KCHUNKS * WCHUNK_BY];
__device__ __align__(256) float  g_h[(size_t)NM * NO];
__device__ __align__(256) float2 g_segstate[NSEG * NCHAN];

// ---------------------------------------------------------------- helpers
__device__ __forceinline__ uint32_t smem_u32(const void* p) {
    uint32_t a;
    asm("{ .reg .u64 t; cvta.to.shared.u64 t, %1; cvt.u32.u64 %0, t; }"
        : "=r"(a) : "l"(p));
    return a;
}
__device__ __forceinline__ void cpasync16(uint32_t s, const void* g) {
    asm volatile("cp.async.cg.shared.global [%0], [%1], 16;\n" :: "r"(s), "l"(g));
}
#define CP_COMMIT()  asm volatile("cp.async.commit_group;" ::: "memory")
#define CP_WAIT(n)   asm volatile("cp.async.wait_group %0;" :: "n"(n) : "memory")

#define MBAR_INIT(a, c) \
    asm volatile("mbarrier.init.shared.b64 [%0], %1;" :: "r"(a), "r"((uint32_t)(c)) : "memory")
#define MBAR_EXPECT_TX(a, b) \
    asm volatile("mbarrier.arrive.expect_tx.shared.b64 _, [%0], %1;" \
                 :: "r"(a), "r"((uint32_t)(b)) : "memory")
__device__ __forceinline__ void mbar_wait(uint32_t addr, uint32_t parity) {
    asm volatile(
        "{\n .reg .pred P;\n"
        "W_%=: mbarrier.try_wait.parity.acquire.cta.shared::cta.b64 P, [%0], %1;\n"
        " @!P bra W_%=;\n}"
        :: "r"(addr), "r"(parity) : "memory");
}
__device__ __forceinline__ void bulk_ld(uint32_t dst, const void* src,
                                        uint32_t bytes, uint32_t mbar) {
    asm volatile(
        "cp.async.bulk.shared::cluster.global.mbarrier::complete_tx::bytes "
        "[%0], [%1], %2, [%3];"
        :: "r"(dst), "l"(src), "r"(bytes), "r"(mbar) : "memory");
}
__device__ __forceinline__ void ldsm_x4(uint32_t* r, uint32_t addr) {
    asm volatile("ldmatrix.sync.aligned.m8n8.x4.shared.b16 {%0,%1,%2,%3}, [%4];"
                 : "=r"(r[0]), "=r"(r[1]), "=r"(r[2]), "=r"(r[3]) : "r"(addr));
}
__device__ __forceinline__ void ldsm_x2(uint32_t* r, uint32_t addr) {
    asm volatile("ldmatrix.sync.aligned.m8n8.x2.shared.b16 {%0,%1}, [%2];"
                 : "=r"(r[0]), "=r"(r[1]) : "r"(addr));
}
__device__ __forceinline__ void mma16816h(float* d, const uint32_t* a, const uint32_t* b) {
    asm volatile(
        "mma.sync.aligned.m16n8k16.row.col.f32.f16.f16.f32 "
        "{%0,%1,%2,%3}, {%4,%5,%6,%7}, {%8,%9}, {%0,%1,%2,%3};"
        : "+f"(d[0]), "+f"(d[1]), "+f"(d[2]), "+f"(d[3])
        : "r"(a[0]), "r"(a[1]), "r"(a[2]), "r"(a[3]), "r"(b[0]), "r"(b[1]));
}
__device__ __host__ __forceinline__ uint32_t swz_off(int row, int seg) {
    return (uint32_t)(row * 64 + ((seg ^ (row & 3)) << 4));
}

// ---------------------------------------------------------------- convert+pack W
__global__ __launch_bounds__(256)
void snn_convW(const float* __restrict__ W) {
    int idx = blockIdx.x * 256 + threadIdx.x;     // 0..16383
    int n   = idx >> 6;                           // 0..255
    int k0  = (idx & 63) << 3;                    // 0..504 step 8
    float4 v0 = *reinterpret_cast<const float4*>(W + (size_t)n * NI + k0);
    float4 v1 = *reinterpret_cast<const float4*>(W + (size_t)n * NI + k0 + 4);
    float xs[8] = {v0.x, v0.y, v0.z, v0.w, v1.x, v1.y, v1.z, v1.w};
    __align__(16) __half hh[8];
#pragma unroll
    for (int i = 0; i < 8; i++) hh[i] = __float2half_rn(xs[i]);
    int kc  = k0 >> 5;
    int seg = (k0 & 31) >> 3;
    *reinterpret_cast<uint4*>(g_Wpk + (size_t)kc * WCHUNK_BY + swz_off(n, seg))
        = *reinterpret_cast<uint4*>(hh);
}

// ---------------------------------------------------------------- GEMM
// BM=64, BN=256, BK=32, 16 chunks, 256 threads (8 warps: 2Mx4N, warp 32x64).
// Single fp16 pass. A: 512x 16B cp.async + in-smem cvt. W: one 16KB bulk.
#define ST_A32  0            // 64 rows x 128B (linear fp32)
#define ST_A16  (8 * 1024)   // 64 rows x 64B  (swizzled fp16)
#define ST_W    (12 * 1024)  // 256 rows x 64B (swizzled fp16)
#define STAGE_SZ (28 * 1024)
#define HDR      1024
#define SMEM_DYN (HDR + 2 * STAGE_SZ)   // 57KB -> 2 CTAs/SM

__device__ __forceinline__ void issue_stage(uint32_t st, uint32_t mbar,
                                            const float* __restrict__ Ain,
                                            int bm, int kc) {
    const int tid = threadIdx.x;
    if (tid == 0) {
        MBAR_EXPECT_TX(mbar, WCHUNK_BY);
        bulk_ld(st + ST_W, g_Wpk + (size_t)kc * WCHUNK_BY, WCHUNK_BY, mbar);
    }
    // A fp32: 64 rows x 8 segs of 16B = 512 ops -> 2/thread (linear layout)
#pragma unroll
    for (int i = 0; i < 2; i++) {
        int idx = tid * 2 + i;
        int row = idx >> 3;            // 0..63
        int seg = idx & 7;             // 16B segment (4 floats)
        cpasync16(st + ST_A32 + (uint32_t)(row * 128 + seg * 16),
                  Ain + (size_t)(bm + row) * NI + kc * 32 + seg * 4);
    }
    CP_COMMIT();
}

__global__ __launch_bounds__(256, 2)
void snn_gemm_mma(const float* __restrict__ Ain) {
    extern __shared__ char smem_raw[];
    const uint32_t sbase = smem_u32(smem_raw);
    const uint32_t mbar[2] = {sbase, sbase + 8};
    const uint32_t stg[2]  = {sbase + HDR, sbase + HDR + STAGE_SZ};

    const int tid   = threadIdx.x;
    const int lane  = tid & 31;
    const int wid   = tid >> 5;          // 0..7
    const int warpM = wid >> 2;          // 0..1 -> 32 rows
    const int warpN = wid & 3;           // 0..3 -> 64 cols
    const int bm    = blockIdx.x * 64;

    if (tid == 0) { MBAR_INIT(mbar[0], 1); MBAR_INIT(mbar[1], 1); }
    __syncthreads();

    float c[2][8][4];
#pragma unroll
    for (int mt = 0; mt < 2; mt++)
#pragma unroll
        for (int nt = 0; nt < 8; nt++)
#pragma unroll
            for (int r = 0; r < 4; r++)
                c[mt][nt][r] = 0.0f;

    const int a_row = warpM * 32 + (lane & 15);
    const int a_sel = lane >> 4;
    const int bl    = lane & 15;
    const int b_rr  = bl & 7;
    const int b_sel = (bl >> 3) & 1;

    const int cv_row = tid >> 2;     // A cvt: 64 rows x 4 thr/row, 8 fp32 each
    const int cv_seg = tid & 3;

    issue_stage(stg[0], mbar[0], Ain, bm, 0);
    issue_stage(stg[1], mbar[1], Ain, bm, 1);

    uint32_t ph[2] = {0, 0};

    for (int kc = 0; kc < KCHUNKS; kc++) {
        const int s = kc & 1;
        const uint32_t cur = stg[s];
        char* const curp = smem_raw + HDR + (size_t)s * STAGE_SZ;

        if (kc < KCHUNKS - 1) { CP_WAIT(1); } else { CP_WAIT(0); }
        mbar_wait(mbar[s], ph[s]);
        ph[s] ^= 1;
        __syncthreads();

        // convert A fp32 -> fp16 (swizzled)
        {
            const float4* sp = reinterpret_cast<const float4*>(
                curp + ST_A32 + cv_row * 128 + cv_seg * 32);
            float4 x0 = sp[0], x1 = sp[1];
            __align__(16) __half2 hh[4];
            hh[0] = __floats2half2_rn(x0.x, x0.y);
            hh[1] = __floats2half2_rn(x0.z, x0.w);
            hh[2] = __floats2half2_rn(x1.x, x1.y);
            hh[3] = __floats2half2_rn(x1.z, x1.w);
            *reinterpret_cast<uint4*>(curp + ST_A16 + swz_off(cv_row, cv_seg))
                = *reinterpret_cast<const uint4*>(hh);
        }
        __syncthreads();

        // mma over the chunk (single fp16 pass)
#pragma unroll
        for (int kk = 0; kk < 2; kk++) {
            uint32_t af[2][4];
#pragma unroll
            for (int mt = 0; mt < 2; mt++)
                ldsm_x4(af[mt], cur + ST_A16 + swz_off(a_row + mt * 16, 2 * kk + a_sel));

#pragma unroll
            for (int h = 0; h < 2; h++) {
                uint32_t bh[4][2];
#pragma unroll
                for (int q = 0; q < 4; q++) {
                    int row = warpN * 64 + (h * 4 + q) * 8 + b_rr;
                    ldsm_x2(bh[q], cur + ST_W + swz_off(row, 2 * kk + b_sel));
                }
#pragma unroll
                for (int mt = 0; mt < 2; mt++)
#pragma unroll
                    for (int q = 0; q < 4; q++)
                        mma16816h(c[mt][h * 4 + q], af[mt], bh[q]);
            }
        }
        __syncthreads();   // all reads of stage s done

        if (kc + 2 < KCHUNKS)
            issue_stage(cur, mbar[s], Ain, bm, kc + 2);
    }

    // epilogue: fragments -> g_h
    const int g = lane >> 2;
    const int q = lane & 3;
#pragma unroll
    for (int mt = 0; mt < 2; mt++) {
#pragma unroll
        for (int nt = 0; nt < 8; nt++) {
            int r0  = bm + warpM * 32 + mt * 16 + g;
            int col = warpN * 64 + nt * 8 + q * 2;
            *reinterpret_cast<float2*>(g_h + (size_t)r0 * NO + col)
                = make_float2(c[mt][nt][0], c[mt][nt][1]);
            *reinterpret_cast<float2*>(g_h + (size_t)(r0 + 8) * NO + col)
                = make_float2(c[mt][nt][2], c[mt][nt][3]);
        }
    }
}

// ---------------------------------------------------------------- segmented scan
__global__ __launch_bounds__(256)
void snn_scan1() {
    const int gidx = blockIdx.x * 256 + threadIdx.x;   // 0..131071
    const int seg  = gidx >> 14;
    const int chan = gidx & (NCHAN - 1);
    const int b    = chan >> 8;
    const int o    = chan & 255;

    const float* hp = g_h + (size_t)b * NT * NO + (size_t)(seg * SEGL) * NO + o;

    float flt = 0.0f, acc = 0.0f;
    for (int t = 0; t < SEGL; t += 25) {
        float hv[25];
#pragma unroll
        for (int j = 0; j < 25; j++) hv[j] = hp[(size_t)(t + j) * NO];
#pragma unroll
        for (int j = 0; j < 25; j++) {
            float na = fmaf(BETA, acc, flt);
            flt = fmaf(ALPHA, flt, hv[j]);
            acc = na;
        }
    }
    g_segstate[seg * NCHAN + chan] = make_float2(flt, acc);
}

struct P3 { float A, B, C; };
__host__ __device__ constexpr P3 seg_prop() {
    float f1 = 1.0f, o1 = 0.0f, o2 = 1.0f;
    for (int j = 0; j < SEGL; j++) {
        o1 = BETA * o1 + f1;
        f1 = ALPHA * f1;
        o2 = BETA * o2;
    }
    return {f1, o2, o1};
}

__global__ __launch_bounds__(256)
void snn_scan3(float* __restrict__ out) {
    const int gidx = blockIdx.x * 256 + threadIdx.x;
    const int seg  = gidx >> 14;
    const int chan = gidx & (NCHAN - 1);
    const int b    = chan >> 8;
    const int o    = chan & 255;

    constexpr P3 P1 = seg_prop();

    float flt = 0.0f, acc = 0.0f;
    {
        float Aj = 1.0f, Bj = 1.0f, Cj = 0.0f;   // P^0 = I
        for (int j = 0; j < seg; j++) {          // s = seg-1-j
            float2 st = g_segstate[(seg - 1 - j) * NCHAN + chan];
            flt += Aj * st.x;
            acc += Cj * st.x + Bj * st.y;
            float An = P1.A * Aj;
            float Cn = P1.C * Aj + P1.B * Cj;
            float Bn = P1.B * Bj;
            Aj = An; Bj = Bn; Cj = Cn;
        }
    }

    const size_t base = (size_t)b * NT * NO + (size_t)(seg * SEGL) * NO + o;
    const float* hp = g_h + base;
    float*       op = out + base;

    for (int t = 0; t < SEGL; t += 5) {
        float hv[5];
#pragma unroll
        for (int j = 0; j < 5; j++) hv[j] = hp[(size_t)(t + j) * NO];
#pragma unroll
        for (int j = 0; j < 5; j++) {
            float na = fmaf(BETA, acc, flt);   // uses OLD flt
            flt = fmaf(ALPHA, flt, hv[j]);
            acc = na;
            op[(size_t)(t + j) * NO] = acc;
        }
    }
}

// ---------------------------------------------------------------- launch
extern "C" void kernel_launch(void* const* d_in, const int* in_sizes, int n_in,
                              void* d_out, int out_size) {
    const float* inputs = (const float*)d_in[0];   // (64,1000,512) f32
    const float* W      = (const float*)d_in[1];   // (256,512) f32
    float* out          = (float*)d_out;           // (64,1000,256) f32
    (void)in_sizes; (void)n_in; (void)out_size;

    cudaFuncSetAttribute(snn_gemm_mma, cudaFuncAttributeMaxDynamicSharedMemorySize, SMEM_DYN);

    snn_convW<<<64, 256>>>(W);
    snn_gemm_mma<<<NM / 64, 256, SMEM_DYN>>>(inputs);
    snn_scan1<<<512, 256>>>();
    snn_scan3<<<512, 256>>>(out);
}